// round 3
// baseline (speedup 1.0000x reference)
#include <cuda_runtime.h>

static constexpr int CHW    = 3 * 128 * 128;   // 49152 floats per (n) image
static constexpr int CHW4   = CHW / 4;         // 12288 float4
static constexpr int S      = 16;
static constexpr int N      = 64;
static constexpr int CHUNKS = 6;
static constexpr int CHUNK4 = CHW4 / CHUNKS;   // 2048 float4 = 32 KB
static constexpr int GRID   = N * CHUNKS;      // 384 blocks

// partials[(n*S + s)*CHUNKS + c]
__device__ float        g_partial[N * S * CHUNKS];
__device__ unsigned int g_count = 0;

__device__ __forceinline__ float ldcg(const float* p) {
    float v;
    asm volatile("ld.global.cg.f32 %0, [%1];" : "=f"(v) : "l"(p));
    return v;
}

__global__ __launch_bounds__(512)
void fused_min_dist_kernel(const float* __restrict__ inputs,
                           const float* __restrict__ samples,
                           float* __restrict__ out) {
    const int blk = blockIdx.x;           // 0..383
    const int n   = blk / CHUNKS;
    const int c   = blk % CHUNKS;
    const int w   = threadIdx.x >> 5;     // warp id == sample index s (16 warps)
    const int l   = threadIdx.x & 31;

    const float4* __restrict__ in4 =
        reinterpret_cast<const float4*>(inputs + (size_t)n * CHW) + (size_t)c * CHUNK4;
    const float4* __restrict__ sm4 =
        reinterpret_cast<const float4*>(samples + ((size_t)n * S + w) * CHW) + (size_t)c * CHUNK4;

    // Each warp streams its own sample; the input chunk is shared by all 16
    // warps through L1 (read from L2/DRAM once per block).
    float acc = 0.0f;
    #pragma unroll 8
    for (int i = l; i < CHUNK4; i += 32) {
        float4 a = in4[i];
        float4 b = sm4[i];
        float dx = b.x - a.x;
        float dy = b.y - a.y;
        float dz = b.z - a.z;
        float dw = b.w - a.w;
        acc = fmaf(dx, dx, acc);
        acc = fmaf(dy, dy, acc);
        acc = fmaf(dz, dz, acc);
        acc = fmaf(dw, dw, acc);
    }

    // Warp-level sum -> one partial per (n, s, chunk)
    #pragma unroll
    for (int o = 16; o > 0; o >>= 1)
        acc += __shfl_down_sync(0xffffffffu, acc, o);
    if (l == 0)
        g_partial[((size_t)n * S + w) * CHUNKS + c] = acc;

    // ---- last-block-finishes final reduction (no second launch) ----
    __shared__ bool is_last;
    __threadfence();              // make this thread's global writes visible
    __syncthreads();
    if (threadIdx.x == 0) {
        // atomicInc wraps to 0 when old == GRID-1 -> self-resetting counter
        unsigned int prev = atomicInc(&g_count, GRID - 1);
        is_last = (prev == GRID - 1);
    }
    __syncthreads();

    if (is_last) {
        __shared__ float sh[N * S];
        // 512 threads cover the 1024 (n,s) pairs: sum the 6 chunk partials.
        for (int p = threadIdx.x; p < N * S; p += 512) {
            float sum = 0.0f;
            #pragma unroll
            for (int cc = 0; cc < CHUNKS; cc++)
                sum += ldcg(&g_partial[(size_t)p * CHUNKS + cc]);  // bypass L1
            sh[p] = sum;
        }
        __syncthreads();

        __shared__ float mins[N];
        if (threadIdx.x < N) {
            const int nn = threadIdx.x;
            float m = sh[nn * S];
            #pragma unroll
            for (int s = 1; s < S; s++)
                m = fminf(m, sh[nn * S + s]);
            mins[nn] = m;
        }
        __syncthreads();

        if (threadIdx.x == 0) {
            float total = 0.0f;
            #pragma unroll
            for (int nn = 0; nn < N; nn++)
                total += mins[nn];      // fixed order -> deterministic
            out[0] = total;
        }
    }
}

extern "C" void kernel_launch(void* const* d_in, const int* in_sizes, int n_in,
                              void* d_out, int out_size) {
    const float* inputs  = (const float*)d_in[0];   // [64,3,128,128]
    const float* samples = (const float*)d_in[1];   // [64,16,3,128,128]
    float* out = (float*)d_out;

    fused_min_dist_kernel<<<GRID, 512>>>(inputs, samples, out);
}